// round 14
// baseline (speedup 1.0000x reference)
#include <cuda_runtime.h>
#include <cstdint>

#define D 200
#define NREL 474
#define NTAB 948
#define VMAX 100000
#define EMAX 1000000
#define THREADS 512
#define NCTA 148
#define TILE 64            // rows per CTA tile (8 producer warps x 8 rows)
#define CHUNK 676          // ceil(VMAX/NCTA)

typedef unsigned long long ull;

// ---- device scratch (no cudaMalloc allowed) ----
__device__ __align__(16) float g_Mtab[NTAB * D];
__device__ __align__(16) float g_Weff[D * D];
__device__ __align__(16) float2 g_sedge[EMAX];
__device__ int g_cnt[VMAX];
__device__ int g_off[VMAX + 1];
__device__ int g_cursor[VMAX];
__device__ int g_bsum[NCTA];
__device__ int g_boff[NCTA];
__device__ float g_sum[D], g_sumsq[D];
__device__ unsigned g_barGen, g_barCnt;

// ---- packed f32x2 ----
__device__ __forceinline__ ull fma2(ull a, ull b, ull c) {
    ull d;
    asm("fma.rn.f32x2 %0, %1, %2, %3;" : "=l"(d) : "l"(a), "l"(b), "l"(c));
    return d;
}
__device__ __forceinline__ ull pack2(float lo, float hi) {
    ull d;
    asm("mov.b64 %0, {%1, %2};" : "=l"(d) : "f"(lo), "f"(hi));
    return d;
}
__device__ __forceinline__ void unpack2(ull v, float& lo, float& hi) {
    asm("mov.b64 {%0, %1}, %2;" : "=f"(lo), "=f"(hi) : "l"(v));
}

// ---- generation grid barrier (all 148 CTAs co-resident) ----
__device__ __forceinline__ void grid_bar() {
    __syncthreads();
    if (threadIdx.x == 0) {
        unsigned gen = *(volatile unsigned*)&g_barGen;
        __threadfence();
        if (atomicAdd(&g_barCnt, 1u) == NCTA - 1) {
            g_barCnt = 0;
            __threadfence();
            atomicExch(&g_barGen, gen + 1);
        } else {
            while (*(volatile unsigned*)&g_barGen == gen) __nanosleep(32);
        }
    }
    __syncthreads();
    __threadfence();   // gpu-scope: flush L1D -> no stale lines across phases
}

// ============================================================================
__global__ void __launch_bounds__(THREADS, 1)
mega_kernel(const float* __restrict__ x,
            const float* __restrict__ rel_repr,
            const float* __restrict__ edge_norm,
            const float* __restrict__ in_w,
            const float* __restrict__ out_w,
            const float* __restrict__ loop_w,
            const float* __restrict__ w_rel,
            const float* __restrict__ loop_rel,
            const float* __restrict__ bias,
            const float* __restrict__ bn_w,
            const float* __restrict__ bn_b,
            const int* __restrict__ edge_type,
            const int* __restrict__ dst,
            float* __restrict__ out, int V, int E) {
    extern __shared__ float dynF[];          // [0,D*D): W ; [D*D, +TILE*D): x tile
    float* xsF = dynF + D * D;
    __shared__ int   ism[THREADS];
    __shared__ int   s2[256];
    __shared__ float fred[THREADS];
    __shared__ float rs[D];
    __shared__ int   wflag[8];               // producer tile counters

    const int tid  = threadIdx.x;
    const int cta  = blockIdx.x;
    const int lane = tid & 31;
    const int team = tid >> 5;               // 16 warps
    const int cg   = (lane < 25) ? lane : 24;
    const bool alane = (lane < 25);
    const int j0   = cg * 8;                 // 8 cols per lane
    const int halfE = E / 2;
    float* rel_out = out + (size_t)V * D;

    // ---------------- phase 0: zero ----------------
    for (int i = cta * THREADS + tid; i < V; i += NCTA * THREADS) g_cnt[i] = 0;
    if (cta == 0 && tid < D) { g_sum[tid] = 0.f; g_sumsq[tid] = 0.f; }
    if (tid < 8) wflag[tid] = 0;
    grid_bar();

    // ---------------- phase 1: histogram of dst ----------------
    for (int e = cta * THREADS + tid; e < E; e += NCTA * THREADS)
        atomicAdd(&g_cnt[dst[e]], 1);
    grid_bar();

    // ---------------- phase 2: scan ----------------
    const int c0 = cta * CHUNK;
    int i0 = c0 + tid * 2;
    bool v0ok = (tid * 2 < CHUNK) && (i0 < V);
    bool v1ok = (tid * 2 + 1 < CHUNK) && (i0 + 1 < V);
    int ca = v0ok ? g_cnt[i0] : 0;
    int cb = v1ok ? g_cnt[i0 + 1] : 0;
    int local = ca + cb;
    ism[tid] = local;
    __syncthreads();
    for (int s = 1; s < THREADS; s <<= 1) {
        int u = (tid >= s) ? ism[tid - s] : 0;
        __syncthreads();
        ism[tid] += u;
        __syncthreads();
    }
    if (tid == THREADS - 1) g_bsum[cta] = ism[THREADS - 1];
    grid_bar();

    if (cta == 0) {
        int v = (tid < NCTA) ? g_bsum[tid] : 0;
        if (tid < 256) s2[tid] = v;
        __syncthreads();
        for (int s = 1; s < 256; s <<= 1) {
            int u = (tid >= s && tid < 256) ? s2[tid - s] : 0;
            __syncthreads();
            if (tid < 256) s2[tid] += u;
            __syncthreads();
        }
        if (tid < NCTA) g_boff[tid] = s2[tid] - v;
        if (tid == 0) g_off[V] = E;
    }
    grid_bar();

    {
        int base = ism[tid] - local + g_boff[cta];
        if (v0ok) { g_off[i0] = base;          g_cursor[i0] = base; }
        if (v1ok) { g_off[i0 + 1] = base + ca; g_cursor[i0 + 1] = base + ca; }
    }
    grid_bar();

    // ---------------- phase 3: sortscatter + prep ----------------
    for (int e = cta * THREADS + tid; e < E; e += NCTA * THREADS) {
        int v = dst[e];
        int row = edge_type[e] + ((e >= halfE) ? NREL : 0);
        int pos = atomicAdd(&g_cursor[v], 1);
        g_sedge[pos] = make_float2(__int_as_float(row), edge_norm[e]);
    }

    {   // prep: 4 tasks per weight sweep (scratch = xsF)
        const int nb = (NREL + 3) / 4;       // 119
        const int totalB = nb * 2 + (D / 4) + nb;
        for (int bb = cta; bb < totalB; bb += NCTA) {
            if (bb < 2 * nb) {
                int hh = bb / nb;
                int b4 = (bb % nb) * 4;
                const float* W = hh ? out_w : in_w;
                for (int i = tid; i < 4 * D; i += THREADS) {
                    int j = i / D, k = i - j * D;
                    int t = b4 + j;
                    xsF[i] = (t < NREL) ? rel_repr[t * D + k] : 0.f;
                }
                __syncthreads();
                float acc[4] = {0.f, 0.f, 0.f, 0.f};
                if (tid < D) {
                    for (int k = 0; k < D; k++) {
                        float wv = W[k * D + tid];
                        #pragma unroll
                        for (int j = 0; j < 4; j++)
                            acc[j] = fmaf(xsF[j * D + k], wv, acc[j]);
                    }
                }
                float ee[4], inv[4];
                #pragma unroll
                for (int j = 0; j < 4; j++) {
                    fred[tid] = (tid < D) ? acc[j] : -1e30f;
                    __syncthreads();
                    for (int s = 256; s > 0; s >>= 1) {
                        if (tid < s) fred[tid] = fmaxf(fred[tid], fred[tid + s]);
                        __syncthreads();
                    }
                    float mx = fred[0];
                    __syncthreads();
                    ee[j] = (tid < D) ? expf(acc[j] - mx) : 0.f;
                    fred[tid] = ee[j];
                    __syncthreads();
                    for (int s = 256; s > 0; s >>= 1) {
                        if (tid < s) fred[tid] += fred[tid + s];
                        __syncthreads();
                    }
                    inv[j] = 1.f / (fred[0] * 3.f);
                    __syncthreads();
                }
                if (tid < D) {
                    #pragma unroll
                    for (int j = 0; j < 4; j++) {
                        int t = b4 + j;
                        if (t < NREL)
                            g_Mtab[(hh * NREL + t) * D + tid] = ee[j] * inv[j];
                    }
                }
                __syncthreads();
            } else if (bb < 2 * nb + D / 4) {
                int kk0 = (bb - 2 * nb) * 4;
                if (tid < D) rs[tid] = loop_rel[tid];
                __syncthreads();
                if (tid < D) {
                    float acc[4] = {0.f, 0.f, 0.f, 0.f};
                    for (int m = 0; m < D; m++) {
                        float wv = loop_w[m * D + tid];
                        #pragma unroll
                        for (int j = 0; j < 4; j++) {
                            int mm = m + kk0 + j;
                            if (mm >= D) mm -= D;
                            acc[j] = fmaf(rs[mm], wv, acc[j]);
                        }
                    }
                    #pragma unroll
                    for (int j = 0; j < 4; j++)
                        g_Weff[(kk0 + j) * D + tid] = acc[j] * (1.f / 3.f);
                }
                __syncthreads();
            } else {
                int b4 = (bb - 2 * nb - D / 4) * 4;
                for (int i = tid; i < 4 * D; i += THREADS) {
                    int j = i / D, k = i - j * D;
                    int t = b4 + j;
                    xsF[i] = (t < NREL) ? rel_repr[t * D + k] : 0.f;
                }
                __syncthreads();
                if (tid < D) {
                    float acc[4] = {0.f, 0.f, 0.f, 0.f};
                    for (int k = 0; k < D; k++) {
                        float wv = w_rel[k * D + tid];
                        #pragma unroll
                        for (int j = 0; j < 4; j++)
                            acc[j] = fmaf(xsF[j * D + k], wv, acc[j]);
                    }
                    #pragma unroll
                    for (int j = 0; j < 4; j++)
                        if (b4 + j < NREL) rel_out[(b4 + j) * D + tid] = acc[j];
                }
                __syncthreads();
            }
        }
    }
    grid_bar();

    // ======== phase 4: warp-specialized GEMM (warps 0-7) + gather (8-15) ======
    for (int i = tid; i < D * D; i += THREADS) dynF[i] = g_Weff[i];
    __syncthreads();

    {
        float sS[8], sQ[8];
        #pragma unroll
        for (int c = 0; c < 8; c++) { sS[c] = 0.f; sQ[c] = 0.f; }

        if (team < 8) {
            // ---------------- producers: GEMM out = x@Weff + bias ----------------
            const int g = team;
            float b0[8];
            #pragma unroll
            for (int c = 0; c < 8; c++) b0[c] = bias[j0 + c];
            const float* wb = dynF + j0;
            int tl = 0;
            for (int tile = cta; tile * TILE < V; tile += NCTA, tl++) {
                int row0 = tile * TILE;
                // stage x tile (8 warps / 256 threads, coalesced float4)
                asm volatile("bar.sync 1, 256;" ::: "memory");
                for (int i = tid; i < TILE * 50; i += 256) {
                    int r = row0 + i / 50;
                    float4 v = (r < V)
                        ? reinterpret_cast<const float4*>(x)[(size_t)r * 50 + (i % 50)]
                        : make_float4(0.f, 0.f, 0.f, 0.f);
                    reinterpret_cast<float4*>(xsF)[i] = v;
                }
                asm volatile("bar.sync 1, 256;" ::: "memory");

                // GEMM: 8 rows x 8 cols/lane, col-paired FFMA2
                ull acc[32];
                #pragma unroll
                for (int i = 0; i < 32; i++) acc[i] = 0ull;
                const float* xb = xsF + g * 8 * D;
                #pragma unroll 2
                for (int k = 0; k < D; k += 2) {
                    ulonglong2 wA0 = *reinterpret_cast<const ulonglong2*>(wb + k * D);
                    ulonglong2 wB0 = *reinterpret_cast<const ulonglong2*>(wb + k * D + 4);
                    ulonglong2 wA1 = *reinterpret_cast<const ulonglong2*>(wb + (k + 1) * D);
                    ulonglong2 wB1 = *reinterpret_cast<const ulonglong2*>(wb + (k + 1) * D + 4);
                    #pragma unroll
                    for (int r = 0; r < 8; r++) {
                        float2 xv = *reinterpret_cast<const float2*>(xb + r * D + k);
                        ull x0 = pack2(xv.x, xv.x);
                        ull x1 = pack2(xv.y, xv.y);
                        acc[r * 4 + 0] = fma2(x0, wA0.x, acc[r * 4 + 0]);
                        acc[r * 4 + 1] = fma2(x0, wA0.y, acc[r * 4 + 1]);
                        acc[r * 4 + 2] = fma2(x0, wB0.x, acc[r * 4 + 2]);
                        acc[r * 4 + 3] = fma2(x0, wB0.y, acc[r * 4 + 3]);
                        acc[r * 4 + 0] = fma2(x1, wA1.x, acc[r * 4 + 0]);
                        acc[r * 4 + 1] = fma2(x1, wA1.y, acc[r * 4 + 1]);
                        acc[r * 4 + 2] = fma2(x1, wB1.x, acc[r * 4 + 2]);
                        acc[r * 4 + 3] = fma2(x1, wB1.y, acc[r * 4 + 3]);
                    }
                }
                #pragma unroll
                for (int r = 0; r < 8; r++) {
                    int vrow = row0 + g * 8 + r;
                    if (alane && vrow < V) {
                        float v[8];
                        unpack2(acc[r * 4 + 0], v[0], v[1]);
                        unpack2(acc[r * 4 + 1], v[2], v[3]);
                        unpack2(acc[r * 4 + 2], v[4], v[5]);
                        unpack2(acc[r * 4 + 3], v[6], v[7]);
                        float* op = out + (size_t)vrow * D + j0;
                        *reinterpret_cast<float4*>(op) = make_float4(
                            v[0] + b0[0], v[1] + b0[1], v[2] + b0[2], v[3] + b0[3]);
                        *reinterpret_cast<float4*>(op + 4) = make_float4(
                            v[4] + b0[4], v[5] + b0[5], v[6] + b0[6], v[7] + b0[7]);
                    }
                }
                __threadfence_block();       // order STG before flag
                if (lane == 0) ((volatile int*)wflag)[g] = tl + 1;
            }
        } else {
            // ---------------- consumers: CSR gather RMW + BN stats ----------------
            const int g = team - 8;
            int tl = 0;
            for (int tile = cta; tile * TILE < V; tile += NCTA, tl++) {
                int v0 = tile * TILE + g * 8;
                // wait for paired producer
                while (((volatile int*)wflag)[g] <= tl) __nanosleep(64);
                __threadfence_block();

                int vhi = (v0 + 8 < V) ? v0 + 8 : V;
                if (v0 >= V) continue;
                int eend = g_off[vhi];
                int vq = v0 + lane;
                int ofr = (lane < 9) ? g_off[(vq < V) ? vq : V] : 0;
                int bse = 0, winEnd = -1;
                float2 edv = make_float2(0.f, 0.f);
                int rowm = 0;

                #pragma unroll
                for (int r = 0; r < 8; r++) {
                    int vrow = v0 + r;
                    if (vrow >= V) break;
                    int e0 = __shfl_sync(0xffffffffu, ofr, r);
                    int e1 = __shfl_sync(0xffffffffu, ofr, r + 1);
                    float fa[8] = {0.f, 0.f, 0.f, 0.f, 0.f, 0.f, 0.f, 0.f};
                    int e = e0;
                    while (e < e1) {
                        if (e >= winEnd) {
                            bse = e;
                            edv = (bse + lane < eend) ? g_sedge[bse + lane]
                                                      : make_float2(0.f, 0.f);
                            rowm = __float_as_int(edv.x);
                            winEnd = bse + 32;
                        }
                        int lim = (e1 < winEnd) ? e1 : winEnd;
                        int j = e - bse;
                        int jend = lim - bse;
                        for (; j + 4 <= jend; j += 4) {
                            int r0 = __shfl_sync(0xffffffffu, rowm, j);
                            int r1 = __shfl_sync(0xffffffffu, rowm, j + 1);
                            int r2 = __shfl_sync(0xffffffffu, rowm, j + 2);
                            int r3 = __shfl_sync(0xffffffffu, rowm, j + 3);
                            float n0 = __shfl_sync(0xffffffffu, edv.y, j);
                            float n1 = __shfl_sync(0xffffffffu, edv.y, j + 1);
                            float n2 = __shfl_sync(0xffffffffu, edv.y, j + 2);
                            float n3 = __shfl_sync(0xffffffffu, edv.y, j + 3);
                            const float4* q0 = reinterpret_cast<const float4*>(g_Mtab + r0 * D + j0);
                            const float4* q1 = reinterpret_cast<const float4*>(g_Mtab + r1 * D + j0);
                            const float4* q2 = reinterpret_cast<const float4*>(g_Mtab + r2 * D + j0);
                            const float4* q3 = reinterpret_cast<const float4*>(g_Mtab + r3 * D + j0);
                            float4 a0 = q0[0], c0v = q0[1];
                            float4 a1 = q1[0], c1v = q1[1];
                            float4 a2 = q2[0], c2v = q2[1];
                            float4 a3 = q3[0], c3v = q3[1];
                            fa[0] = fmaf(n0, a0.x, fa[0]); fa[1] = fmaf(n0, a0.y, fa[1]);
                            fa[2] = fmaf(n0, a0.z, fa[2]); fa[3] = fmaf(n0, a0.w, fa[3]);
                            fa[4] = fmaf(n0, c0v.x, fa[4]); fa[5] = fmaf(n0, c0v.y, fa[5]);
                            fa[6] = fmaf(n0, c0v.z, fa[6]); fa[7] = fmaf(n0, c0v.w, fa[7]);
                            fa[0] = fmaf(n1, a1.x, fa[0]); fa[1] = fmaf(n1, a1.y, fa[1]);
                            fa[2] = fmaf(n1, a1.z, fa[2]); fa[3] = fmaf(n1, a1.w, fa[3]);
                            fa[4] = fmaf(n1, c1v.x, fa[4]); fa[5] = fmaf(n1, c1v.y, fa[5]);
                            fa[6] = fmaf(n1, c1v.z, fa[6]); fa[7] = fmaf(n1, c1v.w, fa[7]);
                            fa[0] = fmaf(n2, a2.x, fa[0]); fa[1] = fmaf(n2, a2.y, fa[1]);
                            fa[2] = fmaf(n2, a2.z, fa[2]); fa[3] = fmaf(n2, a2.w, fa[3]);
                            fa[4] = fmaf(n2, c2v.x, fa[4]); fa[5] = fmaf(n2, c2v.y, fa[5]);
                            fa[6] = fmaf(n2, c2v.z, fa[6]); fa[7] = fmaf(n2, c2v.w, fa[7]);
                            fa[0] = fmaf(n3, a3.x, fa[0]); fa[1] = fmaf(n3, a3.y, fa[1]);
                            fa[2] = fmaf(n3, a3.z, fa[2]); fa[3] = fmaf(n3, a3.w, fa[3]);
                            fa[4] = fmaf(n3, c3v.x, fa[4]); fa[5] = fmaf(n3, c3v.y, fa[5]);
                            fa[6] = fmaf(n3, c3v.z, fa[6]); fa[7] = fmaf(n3, c3v.w, fa[7]);
                        }
                        for (; j < jend; j++) {
                            int rr = __shfl_sync(0xffffffffu, rowm, j);
                            float nm = __shfl_sync(0xffffffffu, edv.y, j);
                            const float4* tp = reinterpret_cast<const float4*>(g_Mtab + rr * D + j0);
                            float4 t0 = tp[0], t1 = tp[1];
                            fa[0] = fmaf(nm, t0.x, fa[0]); fa[1] = fmaf(nm, t0.y, fa[1]);
                            fa[2] = fmaf(nm, t0.z, fa[2]); fa[3] = fmaf(nm, t0.w, fa[3]);
                            fa[4] = fmaf(nm, t1.x, fa[4]); fa[5] = fmaf(nm, t1.y, fa[5]);
                            fa[6] = fmaf(nm, t1.z, fa[6]); fa[7] = fmaf(nm, t1.w, fa[7]);
                        }
                        e = lim;
                    }

                    if (alane) {
                        float* op = out + (size_t)vrow * D + j0;
                        float4 p0 = *reinterpret_cast<const float4*>(op);
                        float4 p1 = *reinterpret_cast<const float4*>(op + 4);
                        float v[8] = {p0.x + fa[0], p0.y + fa[1], p0.z + fa[2],
                                      p0.w + fa[3], p1.x + fa[4], p1.y + fa[5],
                                      p1.z + fa[6], p1.w + fa[7]};
                        *reinterpret_cast<float4*>(op) =
                            make_float4(v[0], v[1], v[2], v[3]);
                        *reinterpret_cast<float4*>(op + 4) =
                            make_float4(v[4], v[5], v[6], v[7]);
                        #pragma unroll
                        for (int c = 0; c < 8; c++) {
                            sS[c] += v[c];
                            sQ[c] += v[c] * v[c];
                        }
                    }
                }
            }
        }

        // CTA reduce -> global atomics (producers contribute zeros)
        __syncthreads();
        if (alane) {
            #pragma unroll
            for (int c = 0; c < 8; c++) dynF[team * D + j0 + c] = sS[c];
        }
        __syncthreads();
        if (tid < D) {
            float t = 0.f;
            #pragma unroll
            for (int w = 0; w < 16; w++) t += dynF[w * D + tid];
            atomicAdd(&g_sum[tid], t);
        }
        __syncthreads();
        if (alane) {
            #pragma unroll
            for (int c = 0; c < 8; c++) dynF[team * D + j0 + c] = sQ[c];
        }
        __syncthreads();
        if (tid < D) {
            float t = 0.f;
            #pragma unroll
            for (int w = 0; w < 16; w++) t += dynF[w * D + tid];
            atomicAdd(&g_sumsq[tid], t);
        }
    }
    grid_bar();

    // ---------------- phase 5: BN normalize ----------------
    {
        float invV = 1.f / (float)V;
        if (tid < D) {
            float mean = g_sum[tid] * invV;
            float var = g_sumsq[tid] * invV - mean * mean;
            float sc = bn_w[tid] * rsqrtf(var + 1e-5f);
            rs[tid] = sc;
            fred[tid] = bn_b[tid] - mean * sc;
        }
        __syncthreads();
        int r0 = cta * CHUNK;
        for (int i = tid; i < CHUNK * 50; i += THREADS) {
            int r = r0 + i / 50;
            if (r < V) {
                int c4 = (i % 50) * 4;
                float4* p = reinterpret_cast<float4*>(out + (size_t)r * D + c4);
                float4 v = *p;
                v.x = v.x * rs[c4]     + fred[c4];
                v.y = v.y * rs[c4 + 1] + fred[c4 + 1];
                v.z = v.z * rs[c4 + 2] + fred[c4 + 2];
                v.w = v.w * rs[c4 + 3] + fred[c4 + 3];
                *p = v;
            }
        }
    }
}

// ============================================================================
extern "C" void kernel_launch(void* const* d_in, const int* in_sizes, int n_in,
                              void* d_out, int out_size) {
    const float* x         = (const float*)d_in[0];
    const float* rel_repr  = (const float*)d_in[1];
    const float* edge_norm = (const float*)d_in[2];
    const float* in_w      = (const float*)d_in[3];
    const float* out_w     = (const float*)d_in[4];
    const float* loop_w    = (const float*)d_in[5];
    const float* w_rel     = (const float*)d_in[6];
    const float* loop_rel  = (const float*)d_in[7];
    const float* bias      = (const float*)d_in[8];
    const float* bn_w      = (const float*)d_in[9];
    const float* bn_b      = (const float*)d_in[10];
    const int*   edge_type = (const int*)d_in[11];
    const int*   dst       = (const int*)d_in[12];
    float* out = (float*)d_out;

    int V = in_sizes[0] / D;   // 100000
    int E = in_sizes[2];       // 1000000

    size_t smem = (size_t)(D * D + TILE * D) * sizeof(float);   // 211,200 B
    cudaFuncSetAttribute(mega_kernel,
                         cudaFuncAttributeMaxDynamicSharedMemorySize, (int)smem);

    mega_kernel<<<NCTA, THREADS, smem>>>(x, rel_repr, edge_norm, in_w, out_w,
                                         loop_w, w_rel, loop_rel, bias, bn_w,
                                         bn_b, edge_type, dst, out, V, E);
}

// round 15
// speedup vs baseline: 1.2897x; 1.2897x over previous
#include <cuda_runtime.h>
#include <cuda_bf16.h>
#include <cstdint>

#define D 200
#define NREL 474
#define NTAB 948
#define VMAX 100000
#define EMAX 1000000
#define THREADS 512
#define NCTA 148
#define TILE 32            // GEMM rows per CTA tile
#define PITCH 216          // bf16 row pitch (conflict-free ldmatrix)
#define KROWS 208          // padded K
#define CHUNK 676          // ceil(VMAX/NCTA)

typedef unsigned long long ull;

// ---- device scratch (no cudaMalloc allowed) ----
__device__ __align__(16) float g_Mtab[NTAB * D];
__device__ __align__(16) float g_Weff[D * D];
__device__ __align__(16) float2 g_sedge[EMAX];
__device__ int g_cnt[VMAX];
__device__ int g_off[VMAX + 1];
__device__ int g_cursor[VMAX];
__device__ int g_bsum[NCTA];
__device__ int g_boff[NCTA];
__device__ float g_sum[D], g_sumsq[D];
__device__ unsigned g_barGen, g_barCnt;

__device__ __forceinline__ uint32_t smem_u32(const void* p) {
    uint32_t a;
    asm("{ .reg .u64 t; cvta.to.shared.u64 t, %1; cvt.u32.u64 %0, t; }"
        : "=r"(a) : "l"(p));
    return a;
}
__device__ __forceinline__ void ldsm_x4(uint32_t& r0, uint32_t& r1,
                                        uint32_t& r2, uint32_t& r3, uint32_t a) {
    asm volatile("ldmatrix.sync.aligned.m8n8.x4.shared.b16 {%0,%1,%2,%3}, [%4];"
                 : "=r"(r0), "=r"(r1), "=r"(r2), "=r"(r3) : "r"(a));
}
__device__ __forceinline__ void ldsm_x2t(uint32_t& r0, uint32_t& r1, uint32_t a) {
    asm volatile("ldmatrix.sync.aligned.m8n8.x2.trans.shared.b16 {%0,%1}, [%2];"
                 : "=r"(r0), "=r"(r1) : "r"(a));
}
__device__ __forceinline__ void mma_bf16(float& c0, float& c1, float& c2, float& c3,
                                         uint32_t a0, uint32_t a1, uint32_t a2,
                                         uint32_t a3, uint32_t b0, uint32_t b1) {
    asm volatile(
        "mma.sync.aligned.m16n8k16.row.col.f32.bf16.bf16.f32 "
        "{%0,%1,%2,%3},{%4,%5,%6,%7},{%8,%9},{%0,%1,%2,%3};"
        : "+f"(c0), "+f"(c1), "+f"(c2), "+f"(c3)
        : "r"(a0), "r"(a1), "r"(a2), "r"(a3), "r"(b0), "r"(b1));
}

// ---- generation grid barrier (all 148 CTAs co-resident) ----
__device__ __forceinline__ void grid_bar() {
    __syncthreads();
    if (threadIdx.x == 0) {
        unsigned gen = *(volatile unsigned*)&g_barGen;
        __threadfence();
        if (atomicAdd(&g_barCnt, 1u) == NCTA - 1) {
            g_barCnt = 0;
            __threadfence();
            atomicExch(&g_barGen, gen + 1);
        } else {
            while (*(volatile unsigned*)&g_barGen == gen) __nanosleep(32);
        }
    }
    __syncthreads();
    __threadfence();
}

// ============================================================================
__global__ void __launch_bounds__(THREADS, 1)
mega_kernel(const float* __restrict__ x,
            const float* __restrict__ rel_repr,
            const float* __restrict__ edge_norm,
            const float* __restrict__ in_w,
            const float* __restrict__ out_w,
            const float* __restrict__ loop_w,
            const float* __restrict__ w_rel,
            const float* __restrict__ loop_rel,
            const float* __restrict__ bias,
            const float* __restrict__ bn_w,
            const float* __restrict__ bn_b,
            const int* __restrict__ edge_type,
            const int* __restrict__ dst,
            float* __restrict__ out, int V, int E) {
    extern __shared__ float dynF[];
    __shared__ int   ism[THREADS];
    __shared__ int   s2[256];
    __shared__ float fred[THREADS];
    __shared__ float rs[D];

    const int tid  = threadIdx.x;
    const int cta  = blockIdx.x;
    const int lane = tid & 31;
    const int team = tid >> 5;               // 16 warps
    const int cg   = (lane < 25) ? lane : 24;
    const bool alane = (lane < 25);
    const int j0   = cg * 8;
    const int halfE = E / 2;
    float* rel_out = out + (size_t)V * D;
    float* xsF = dynF;                       // prep scratch (phase 3 only)

    // ---------------- phase 0: zero ----------------
    for (int i = cta * THREADS + tid; i < V; i += NCTA * THREADS) g_cnt[i] = 0;
    if (cta == 0 && tid < D) { g_sum[tid] = 0.f; g_sumsq[tid] = 0.f; }
    grid_bar();

    // ---------------- phase 1: histogram of dst ----------------
    for (int e = cta * THREADS + tid; e < E; e += NCTA * THREADS)
        atomicAdd(&g_cnt[dst[e]], 1);
    grid_bar();

    // ---------------- phase 2: scan ----------------
    const int c0 = cta * CHUNK;
    int i0 = c0 + tid * 2;
    bool v0ok = (tid * 2 < CHUNK) && (i0 < V);
    bool v1ok = (tid * 2 + 1 < CHUNK) && (i0 + 1 < V);
    int ca = v0ok ? g_cnt[i0] : 0;
    int cb = v1ok ? g_cnt[i0 + 1] : 0;
    int local = ca + cb;
    ism[tid] = local;
    __syncthreads();
    for (int s = 1; s < THREADS; s <<= 1) {
        int u = (tid >= s) ? ism[tid - s] : 0;
        __syncthreads();
        ism[tid] += u;
        __syncthreads();
    }
    if (tid == THREADS - 1) g_bsum[cta] = ism[THREADS - 1];
    grid_bar();

    if (cta == 0) {
        int v = (tid < NCTA) ? g_bsum[tid] : 0;
        if (tid < 256) s2[tid] = v;
        __syncthreads();
        for (int s = 1; s < 256; s <<= 1) {
            int u = (tid >= s && tid < 256) ? s2[tid - s] : 0;
            __syncthreads();
            if (tid < 256) s2[tid] += u;
            __syncthreads();
        }
        if (tid < NCTA) g_boff[tid] = s2[tid] - v;
        if (tid == 0) g_off[V] = E;
    }
    grid_bar();

    {
        int base = ism[tid] - local + g_boff[cta];
        if (v0ok) { g_off[i0] = base;          g_cursor[i0] = base; }
        if (v1ok) { g_off[i0 + 1] = base + ca; g_cursor[i0 + 1] = base + ca; }
    }
    grid_bar();

    // ---------------- phase 3: sortscatter + prep ----------------
    for (int e = cta * THREADS + tid; e < E; e += NCTA * THREADS) {
        int v = dst[e];
        int row = edge_type[e] + ((e >= halfE) ? NREL : 0);
        int pos = atomicAdd(&g_cursor[v], 1);
        g_sedge[pos] = make_float2(__int_as_float(row), edge_norm[e]);
    }

    {   // prep: 4 tasks per weight sweep (scratch = xsF)
        const int nb = (NREL + 3) / 4;       // 119
        const int totalB = nb * 2 + (D / 4) + nb;
        for (int bb = cta; bb < totalB; bb += NCTA) {
            if (bb < 2 * nb) {
                int hh = bb / nb;
                int b4 = (bb % nb) * 4;
                const float* W = hh ? out_w : in_w;
                for (int i = tid; i < 4 * D; i += THREADS) {
                    int j = i / D, k = i - j * D;
                    int t = b4 + j;
                    xsF[i] = (t < NREL) ? rel_repr[t * D + k] : 0.f;
                }
                __syncthreads();
                float acc[4] = {0.f, 0.f, 0.f, 0.f};
                if (tid < D) {
                    for (int k = 0; k < D; k++) {
                        float wv = W[k * D + tid];
                        #pragma unroll
                        for (int j = 0; j < 4; j++)
                            acc[j] = fmaf(xsF[j * D + k], wv, acc[j]);
                    }
                }
                float ee[4], inv[4];
                #pragma unroll
                for (int j = 0; j < 4; j++) {
                    fred[tid] = (tid < D) ? acc[j] : -1e30f;
                    __syncthreads();
                    for (int s = 256; s > 0; s >>= 1) {
                        if (tid < s) fred[tid] = fmaxf(fred[tid], fred[tid + s]);
                        __syncthreads();
                    }
                    float mx = fred[0];
                    __syncthreads();
                    ee[j] = (tid < D) ? expf(acc[j] - mx) : 0.f;
                    fred[tid] = ee[j];
                    __syncthreads();
                    for (int s = 256; s > 0; s >>= 1) {
                        if (tid < s) fred[tid] += fred[tid + s];
                        __syncthreads();
                    }
                    inv[j] = 1.f / (fred[0] * 3.f);
                    __syncthreads();
                }
                if (tid < D) {
                    #pragma unroll
                    for (int j = 0; j < 4; j++) {
                        int t = b4 + j;
                        if (t < NREL)
                            g_Mtab[(hh * NREL + t) * D + tid] = ee[j] * inv[j];
                    }
                }
                __syncthreads();
            } else if (bb < 2 * nb + D / 4) {
                int kk0 = (bb - 2 * nb) * 4;
                if (tid < D) rs[tid] = loop_rel[tid];
                __syncthreads();
                if (tid < D) {
                    float acc[4] = {0.f, 0.f, 0.f, 0.f};
                    for (int m = 0; m < D; m++) {
                        float wv = loop_w[m * D + tid];
                        #pragma unroll
                        for (int j = 0; j < 4; j++) {
                            int mm = m + kk0 + j;
                            if (mm >= D) mm -= D;
                            acc[j] = fmaf(rs[mm], wv, acc[j]);
                        }
                    }
                    #pragma unroll
                    for (int j = 0; j < 4; j++)
                        g_Weff[(kk0 + j) * D + tid] = acc[j] * (1.f / 3.f);
                }
                __syncthreads();
            } else {
                int b4 = (bb - 2 * nb - D / 4) * 4;
                for (int i = tid; i < 4 * D; i += THREADS) {
                    int j = i / D, k = i - j * D;
                    int t = b4 + j;
                    xsF[i] = (t < NREL) ? rel_repr[t * D + k] : 0.f;
                }
                __syncthreads();
                if (tid < D) {
                    float acc[4] = {0.f, 0.f, 0.f, 0.f};
                    for (int k = 0; k < D; k++) {
                        float wv = w_rel[k * D + tid];
                        #pragma unroll
                        for (int j = 0; j < 4; j++)
                            acc[j] = fmaf(xsF[j * D + k], wv, acc[j]);
                    }
                    #pragma unroll
                    for (int j = 0; j < 4; j++)
                        if (b4 + j < NREL) rel_out[(b4 + j) * D + tid] = acc[j];
                }
                __syncthreads();
            }
        }
    }
    grid_bar();

    // ======= phase 4: tensor-core GEMM out = x@Weff + bias (bf16 3-pass) =====
    {
        __nv_bfloat16* whi = reinterpret_cast<__nv_bfloat16*>(dynF);
        __nv_bfloat16* wlo = whi + KROWS * PITCH;
        __nv_bfloat16* xhi = wlo + KROWS * PITCH;
        __nv_bfloat16* xlo = xhi + TILE * PITCH;

        // build W hi/lo (once per CTA)
        for (int i = tid; i < KROWS * PITCH; i += THREADS) {
            int k = i / PITCH, n = i % PITCH;
            float v = (k < D && n < D) ? g_Weff[k * D + n] : 0.f;
            __nv_bfloat16 h = __float2bfloat16(v);
            whi[i] = h;
            wlo[i] = __float2bfloat16(v - __bfloat162float(h));
        }
        __syncthreads();

        const uint32_t whiA = smem_u32(whi);
        const uint32_t wloA = smem_u32(wlo);
        const uint32_t xhiA = smem_u32(xhi);
        const uint32_t xloA = smem_u32(xlo);

        const int rowg = team >> 3;          // 0-1
        const int colg = team & 7;           // 0-7
        const int r0l  = rowg * 16;
        const int a_row = r0l + (lane & 7) + ((lane >> 3) & 1) * 8;
        const int a_k8  = (lane >> 4) * 8;
        const int b_koff = (lane & 7) + ((lane >> 3) & 1) * 8;

        const int gr = lane >> 2;            // 0-7
        const int tc = lane & 3;
        float bi0[4], bi1[4];
        #pragma unroll
        for (int i = 0; i < 4; i++) {
            int nt = colg + 8 * i;
            int col = nt * 8 + tc * 2;
            bi0[i] = (col < D) ? bias[col] : 0.f;
            bi1[i] = (col + 1 < D) ? bias[col + 1] : 0.f;
        }

        const int ntiles = (V + TILE - 1) / TILE;
        for (int tile = cta; tile < ntiles; tile += NCTA) {
            int row0 = tile * TILE;
            __syncthreads();
            for (int i = tid; i < TILE * PITCH; i += THREADS) {
                int r = i / PITCH, k = i % PITCH;
                int vrow = row0 + r;
                float v = (vrow < V && k < D) ? x[(size_t)vrow * D + k] : 0.f;
                __nv_bfloat16 h = __float2bfloat16(v);
                xhi[i] = h;
                xlo[i] = __float2bfloat16(v - __bfloat162float(h));
            }
            __syncthreads();

            float c[4][4];
            #pragma unroll
            for (int i = 0; i < 4; i++)
                #pragma unroll
                for (int q = 0; q < 4; q++) c[i][q] = 0.f;

            #pragma unroll
            for (int pass = 0; pass < 3; pass++) {
                uint32_t ab = (pass == 2) ? xloA : xhiA;
                uint32_t bb = (pass == 1) ? wloA : whiA;
                for (int k0 = 0; k0 < KROWS; k0 += 16) {
                    uint32_t a0, a1, a2, a3;
                    ldsm_x4(a0, a1, a2, a3,
                            ab + (uint32_t)((a_row * PITCH + k0 + a_k8) * 2));
                    #pragma unroll
                    for (int i = 0; i < 4; i++) {
                        int nt = colg + 8 * i;
                        if (nt < 26) {
                            uint32_t b0, b1;
                            ldsm_x2t(b0, b1,
                                     bb + (uint32_t)(((k0 + b_koff) * PITCH + nt * 8) * 2));
                            mma_bf16(c[i][0], c[i][1], c[i][2], c[i][3],
                                     a0, a1, a2, a3, b0, b1);
                        }
                    }
                }
            }

            // epilogue: store C + bias
            int vr1 = row0 + r0l + gr;
            int vr2 = vr1 + 8;
            #pragma unroll
            for (int i = 0; i < 4; i++) {
                int nt = colg + 8 * i;
                int col = nt * 8 + tc * 2;
                if (nt < 25) {     // nt==25 covers padded cols 200-207
                    if (vr1 < V) {
                        float2 st = make_float2(c[i][0] + bi0[i], c[i][1] + bi1[i]);
                        *reinterpret_cast<float2*>(out + (size_t)vr1 * D + col) = st;
                    }
                    if (vr2 < V) {
                        float2 st = make_float2(c[i][2] + bi0[i], c[i][3] + bi1[i]);
                        *reinterpret_cast<float2*>(out + (size_t)vr2 * D + col) = st;
                    }
                }
            }
        }
    }
    grid_bar();

    // ---------------- phase 5: gather (2-vertex merged windows) + BN --------
    {
        float sS[8], sQ[8];
        #pragma unroll
        for (int c = 0; c < 8; c++) { sS[c] = 0.f; sQ[c] = 0.f; }

        for (int blk = cta * 16 + team; blk * 8 < V; blk += NCTA * 16) {
            int v0 = blk * 8;
            int vend = (v0 + 8 < V) ? v0 + 8 : V;
            for (int v = v0; v < vend; v += 2) {
                bool hasB = (v + 1 < vend);
                int e0 = g_off[v];
                int e1 = g_off[v + 1];
                int e2 = hasB ? g_off[v + 2] : e1;

                size_t obA = (size_t)v * D + j0;
                float4 pA0 = *reinterpret_cast<const float4*>(out + obA);
                float4 pA1 = *reinterpret_cast<const float4*>(out + obA + 4);
                float4 pB0 = make_float4(0.f, 0.f, 0.f, 0.f), pB1 = pB0;
                size_t obB = (size_t)(v + 1) * D + j0;
                if (hasB) {
                    pB0 = *reinterpret_cast<const float4*>(out + obB);
                    pB1 = *reinterpret_cast<const float4*>(out + obB + 4);
                }

                float accA[8] = {0.f,0.f,0.f,0.f,0.f,0.f,0.f,0.f};
                float accB[8] = {0.f,0.f,0.f,0.f,0.f,0.f,0.f,0.f};

                for (int bse = e0; bse < e2; bse += 32) {
                    int n = e2 - bse; if (n > 32) n = 32;
                    float2 ed = (bse + lane < e2) ? g_sedge[bse + lane]
                                                  : make_float2(0.f, 0.f);
                    int rowm = __float_as_int(ed.x);
                    int nA = e1 - bse;
                    if (nA < 0) nA = 0;
                    if (nA > n) nA = n;

                    #pragma unroll 1
                    for (int seg = 0; seg < 2; seg++) {
                        int js = seg ? nA : 0;
                        int je = seg ? n : nA;
                        float* acc = seg ? accB : accA;
                        int j = js;
                        for (; j + 4 <= je; j += 4) {
                            int r0 = __shfl_sync(0xffffffffu, rowm, j);
                            int r1 = __shfl_sync(0xffffffffu, rowm, j + 1);
                            int r2 = __shfl_sync(0xffffffffu, rowm, j + 2);
                            int r3 = __shfl_sync(0xffffffffu, rowm, j + 3);
                            float n0 = __shfl_sync(0xffffffffu, ed.y, j);
                            float n1 = __shfl_sync(0xffffffffu, ed.y, j + 1);
                            float n2 = __shfl_sync(0xffffffffu, ed.y, j + 2);
                            float n3 = __shfl_sync(0xffffffffu, ed.y, j + 3);
                            const float4* q0 = reinterpret_cast<const float4*>(g_Mtab + r0 * D + j0);
                            const float4* q1 = reinterpret_cast<const float4*>(g_Mtab + r1 * D + j0);
                            const float4* q2 = reinterpret_cast<const float4*>(g_Mtab + r2 * D + j0);
                            const float4* q3 = reinterpret_cast<const float4*>(g_Mtab + r3 * D + j0);
                            float4 a0 = q0[0], c0v = q0[1];
                            float4 a1 = q1[0], c1v = q1[1];
                            float4 a2 = q2[0], c2v = q2[1];
                            float4 a3 = q3[0], c3v = q3[1];
                            acc[0] = fmaf(n0, a0.x, acc[0]); acc[1] = fmaf(n0, a0.y, acc[1]);
                            acc[2] = fmaf(n0, a0.z, acc[2]); acc[3] = fmaf(n0, a0.w, acc[3]);
                            acc[4] = fmaf(n0, c0v.x, acc[4]); acc[5] = fmaf(n0, c0v.y, acc[5]);
                            acc[6] = fmaf(n0, c0v.z, acc[6]); acc[7] = fmaf(n0, c0v.w, acc[7]);
                            acc[0] = fmaf(n1, a1.x, acc[0]); acc[1] = fmaf(n1, a1.y, acc[1]);
                            acc[2] = fmaf(n1, a1.z, acc[2]); acc[3] = fmaf(n1, a1.w, acc[3]);
                            acc[4] = fmaf(n1, c1v.x, acc[4]); acc[5] = fmaf(n1, c1v.y, acc[5]);
                            acc[6] = fmaf(n1, c1v.z, acc[6]); acc[7] = fmaf(n1, c1v.w, acc[7]);
                            acc[0] = fmaf(n2, a2.x, acc[0]); acc[1] = fmaf(n2, a2.y, acc[1]);
                            acc[2] = fmaf(n2, a2.z, acc[2]); acc[3] = fmaf(n2, a2.w, acc[3]);
                            acc[4] = fmaf(n2, c2v.x, acc[4]); acc[5] = fmaf(n2, c2v.y, acc[5]);
                            acc[6] = fmaf(n2, c2v.z, acc[6]); acc[7] = fmaf(n2, c2v.w, acc[7]);
                            acc[0] = fmaf(n3, a3.x, acc[0]); acc[1] = fmaf(n3, a3.y, acc[1]);
                            acc[2] = fmaf(n3, a3.z, acc[2]); acc[3] = fmaf(n3, a3.w, acc[3]);
                            acc[4] = fmaf(n3, c3v.x, acc[4]); acc[5] = fmaf(n3, c3v.y, acc[5]);
                            acc[6] = fmaf(n3, c3v.z, acc[6]); acc[7] = fmaf(n3, c3v.w, acc[7]);
                        }
                        for (; j < je; j++) {
                            int rr = __shfl_sync(0xffffffffu, rowm, j);
                            float nm = __shfl_sync(0xffffffffu, ed.y, j);
                            const float4* tp = reinterpret_cast<const float4*>(g_Mtab + rr * D + j0);
                            float4 t0 = tp[0], t1 = tp[1];
                            acc[0] = fmaf(nm, t0.x, acc[0]); acc[1] = fmaf(nm, t0.y, acc[1]);
                            acc[2] = fmaf(nm, t0.z, acc[2]); acc[3] = fmaf(nm, t0.w, acc[3]);
                            acc[4] = fmaf(nm, t1.x, acc[4]); acc[5] = fmaf(nm, t1.y, acc[5]);
                            acc[6] = fmaf(nm, t1.z, acc[6]); acc[7] = fmaf(nm, t1.w, acc[7]);
                        }
                    }
                }

                if (alane) {
                    accA[0] += pA0.x; accA[1] += pA0.y; accA[2] += pA0.z; accA[3] += pA0.w;
                    accA[4] += pA1.x; accA[5] += pA1.y; accA[6] += pA1.z; accA[7] += pA1.w;
                    *reinterpret_cast<float4*>(out + obA) =
                        make_float4(accA[0], accA[1], accA[2], accA[3]);
                    *reinterpret_cast<float4*>(out + obA + 4) =
                        make_float4(accA[4], accA[5], accA[6], accA[7]);
                    #pragma unroll
                    for (int c = 0; c < 8; c++) {
                        sS[c] += accA[c];
                        sQ[c] += accA[c] * accA[c];
                    }
                    if (hasB) {
                        accB[0] += pB0.x; accB[1] += pB0.y; accB[2] += pB0.z; accB[3] += pB0.w;
                        accB[4] += pB1.x; accB[5] += pB1.y; accB[6] += pB1.z; accB[7] += pB1.w;
                        *reinterpret_cast<float4*>(out + obB) =
                            make_float4(accB[0], accB[1], accB[2], accB[3]);
                        *reinterpret_cast<float4*>(out + obB + 4) =
                            make_float4(accB[4], accB[5], accB[6], accB[7]);
                        #pragma unroll
                        for (int c = 0; c < 8; c++) {
                            sS[c] += accB[c];
                            sQ[c] += accB[c] * accB[c];
                        }
                    }
                }
            }
        }

        // CTA reduce -> global atomics
        __syncthreads();
        if (alane) {
            #pragma unroll
            for (int c = 0; c < 8; c++) dynF[team * D + j0 + c] = sS[c];
        }
        __syncthreads();
        if (tid < D) {
            float t = 0.f;
            #pragma unroll
            for (int w = 0; w < 16; w++) t += dynF[w * D + tid];
            atomicAdd(&g_sum[tid], t);
        }
        __syncthreads();
        if (alane) {
            #pragma unroll
            for (int c = 0; c < 8; c++) dynF[team * D + j0 + c] = sQ[c];
        }
        __syncthreads();
        if (tid < D) {
            float t = 0.f;
            #pragma unroll
            for (int w = 0; w < 16; w++) t += dynF[w * D + tid];
            atomicAdd(&g_sumsq[tid], t);
        }
    }
    grid_bar();

    // ---------------- phase 6: BN normalize ----------------
    {
        float invV = 1.f / (float)V;
        if (tid < D) {
            float mean = g_sum[tid] * invV;
            float var = g_sumsq[tid] * invV - mean * mean;
            float sc = bn_w[tid] * rsqrtf(var + 1e-5f);
            rs[tid] = sc;
            fred[tid] = bn_b[tid] - mean * sc;
        }
        __syncthreads();
        int r0 = cta * CHUNK;
        for (int i = tid; i < CHUNK * 50; i += THREADS) {
            int r = r0 + i / 50;
            if (r < V) {
                int c4 = (i % 50) * 4;
                float4* p = reinterpret_cast<float4*>(out + (size_t)r * D + c4);
                float4 v = *p;
                v.x = v.x * rs[c4]     + fred[c4];
                v.y = v.y * rs[c4 + 1] + fred[c4 + 1];
                v.z = v.z * rs[c4 + 2] + fred[c4 + 2];
                v.w = v.w * rs[c4 + 3] + fred[c4 + 3];
                *p = v;
            }
        }
    }
}

// ============================================================================
extern "C" void kernel_launch(void* const* d_in, const int* in_sizes, int n_in,
                              void* d_out, int out_size) {
    const float* x         = (const float*)d_in[0];
    const float* rel_repr  = (const float*)d_in[1];
    const float* edge_norm = (const float*)d_in[2];
    const float* in_w      = (const float*)d_in[3];
    const float* out_w     = (const float*)d_in[4];
    const float* loop_w    = (const float*)d_in[5];
    const float* w_rel     = (const float*)d_in[6];
    const float* loop_rel  = (const float*)d_in[7];
    const float* bias      = (const float*)d_in[8];
    const float* bn_w      = (const float*)d_in[9];
    const float* bn_b      = (const float*)d_in[10];
    const int*   edge_type = (const int*)d_in[11];
    const int*   dst       = (const int*)d_in[12];
    float* out = (float*)d_out;

    int V = in_sizes[0] / D;   // 100000
    int E = in_sizes[2];       // 1000000

    // smem: 2 W buffers (208*216 bf16) + 2 x buffers (32*216 bf16) = 207,360 B
    size_t smem = (size_t)(2 * KROWS * PITCH + 2 * TILE * PITCH) * 2;
    cudaFuncSetAttribute(mega_kernel,
                         cudaFuncAttributeMaxDynamicSharedMemorySize, (int)smem);

    mega_kernel<<<NCTA, THREADS, smem>>>(x, rel_repr, edge_norm, in_w, out_w,
                                         loop_w, w_rel, loop_rel, bias, bn_w,
                                         bn_b, edge_type, dst, out, V, E);
}